// round 2
// baseline (speedup 1.0000x reference)
#include <cuda_runtime.h>
#include <math_constants.h>

#define N_POINTS 50000
#define CHANNELS 64

// Initialize output to -inf (segment_max identity). Output is poisoned 0xAA
// by the harness, and empty segments must be -inf per JAX semantics.
__global__ void init_out_kernel(float4* __restrict__ out, int n4) {
    int i = blockIdx.x * blockDim.x + threadIdx.x;
    if (i < n4) {
        out[i] = make_float4(-CUDART_INF_F, -CUDART_INF_F, -CUDART_INF_F, -CUDART_INF_F);
    }
}

// Float atomic max via sign-split integer atomics.
// Return value unused -> ptxas emits RED (no return round trip).
//  - non-negatives as int compare correctly -> atomicMax(int)
//  - negatives as uint are inversely ordered -> atomicMin(uint)
//  - init value -inf = 0xFF800000 is int-min among patterns seen on the
//    positive path and uint-max on the negative path, so both work.
__device__ __forceinline__ void atomicMaxFloat(float* addr, float val) {
    if (val >= 0.0f) {
        atomicMax((int*)addr, __float_as_int(val));
    } else {
        atomicMin((unsigned int*)addr, __float_as_uint(val));
    }
}

// 16 threads per edge, 4 channels per thread (float4 gather).
// NOTE: indices are int32 (JAX without x64 downcasts jnp.int64 -> int32).
__global__ void scatter_max_kernel(const float* __restrict__ feat,
                                   const int* __restrict__ idx,
                                   float* __restrict__ out,
                                   int n_edges) {
    long long t = (long long)blockIdx.x * blockDim.x + threadIdx.x;
    int edge = (int)(t >> 4);
    if (edge >= n_edges) return;
    int c4 = (int)(t & 15) << 2;

    // One int2 load fetches both indices of the edge.
    int2 e = __ldg(reinterpret_cast<const int2*>(idx) + edge);
    int o_idx = e.x;
    int i_idx = e.y;

    const float4 v = *reinterpret_cast<const float4*>(feat + (long long)i_idx * CHANNELS + c4);
    float* dst = out + (long long)o_idx * CHANNELS + c4;

    atomicMaxFloat(dst + 0, v.x);
    atomicMaxFloat(dst + 1, v.y);
    atomicMaxFloat(dst + 2, v.z);
    atomicMaxFloat(dst + 3, v.w);
}

extern "C" void kernel_launch(void* const* d_in, const int* in_sizes, int n_in,
                              void* d_out, int out_size) {
    const float* feat = (const float*)d_in[0];   // [N_POINTS, 64] f32
    const int* idx = (const int*)d_in[1];        // [N_EDGES, 2] i32
    float* out = (float*)d_out;                  // [N_POINTS, 64] f32

    int n_edges = in_sizes[1] / 2;

    // Phase 1: init output to -inf
    int n4 = out_size / 4;
    int ib = (n4 + 255) / 256;
    init_out_kernel<<<ib, 256>>>((float4*)out, n4);

    // Phase 2: atomic scatter-max, 16 threads per edge
    long long total_threads = (long long)n_edges * 16;
    int sb = (int)((total_threads + 255) / 256);
    scatter_max_kernel<<<sb, 256>>>(feat, idx, out, n_edges);
}

// round 3
// speedup vs baseline: 5.5039x; 5.5039x over previous
#include <cuda_runtime.h>
#include <math_constants.h>

#define N_POINTS 50000
#define CHANNELS 64
#define CAP 128   // bucket capacity per point; counts ~Poisson(32), max ~66

// Static scratch (no allocations allowed).
__device__ int d_cursor[N_POINTS];
__device__ int d_bucket[N_POINTS * CAP];   // 25.6 MB

// ---------------------------------------------------------------------------
// K1: init out to -inf (segment_max identity; also covers empty segments and
// harness 0xAA poison) and zero the cursors.
// ---------------------------------------------------------------------------
__global__ void init_kernel(float4* __restrict__ out, int n4) {
    int i = blockIdx.x * blockDim.x + threadIdx.x;
    if (i < n4) {
        out[i] = make_float4(-CUDART_INF_F, -CUDART_INF_F, -CUDART_INF_F, -CUDART_INF_F);
    }
    if (i < N_POINTS) {
        d_cursor[i] = 0;
    }
}

// Float atomic max via sign-split integer atomics (RED, no return).
// Used only on the (probability ~0) bucket-overflow fallback path.
__device__ __forceinline__ void atomicMaxFloat(float* addr, float val) {
    if (val >= 0.0f) {
        atomicMax((int*)addr, __float_as_int(val));
    } else {
        atomicMin((unsigned int*)addr, __float_as_uint(val));
    }
}

// ---------------------------------------------------------------------------
// K2: bucket-build. One thread per edge: claim a slot in the destination
// point's bucket and record the source index. 1.6M atomics total
// (vs 102.4M in the direct scatter-max approach).
// ---------------------------------------------------------------------------
__global__ void bucket_kernel(const int* __restrict__ idx,
                              const float* __restrict__ feat,
                              float* __restrict__ out,
                              int n_edges) {
    int e = blockIdx.x * blockDim.x + threadIdx.x;
    if (e >= n_edges) return;

    int2 pr = __ldg(reinterpret_cast<const int2*>(idx) + e);
    int o_idx = pr.x;
    int i_idx = pr.y;

    int pos = atomicAdd(&d_cursor[o_idx], 1);
    if (pos < CAP) {
        d_bucket[o_idx * CAP + pos] = i_idx;
    } else {
        // Exactness fallback: scatter-max this edge directly into out.
        const float4* src = reinterpret_cast<const float4*>(feat + (long long)i_idx * CHANNELS);
        float* dst = out + (long long)o_idx * CHANNELS;
        #pragma unroll
        for (int c = 0; c < CHANNELS / 4; c++) {
            float4 v = __ldg(src + c);
            atomicMaxFloat(dst + 4 * c + 0, v.x);
            atomicMaxFloat(dst + 4 * c + 1, v.y);
            atomicMaxFloat(dst + 4 * c + 2, v.z);
            atomicMaxFloat(dst + 4 * c + 3, v.w);
        }
    }
}

// ---------------------------------------------------------------------------
// K3: dense segment-max. 16 lanes per point, 4 channels (one float4) per lane.
// Gathers are coalesced 256B rows from the L2-resident feature table; the max
// runs entirely in registers. Combines with existing out (absorbs overflow
// fallback writes), then stores.
// ---------------------------------------------------------------------------
__device__ __forceinline__ float4 max4(float4 a, float4 b) {
    return make_float4(fmaxf(a.x, b.x), fmaxf(a.y, b.y),
                       fmaxf(a.z, b.z), fmaxf(a.w, b.w));
}

__global__ void segmax_kernel(const float* __restrict__ feat,
                              float* __restrict__ out) {
    int t = blockIdx.x * blockDim.x + threadIdx.x;
    int p = t >> 4;
    if (p >= N_POINTS) return;
    int c4 = (t & 15) << 2;

    int cnt = d_cursor[p];
    if (cnt > CAP) cnt = CAP;
    const int* bkt = d_bucket + p * CAP;

    float4 acc = make_float4(-CUDART_INF_F, -CUDART_INF_F, -CUDART_INF_F, -CUDART_INF_F);

    int i = 0;
    // 4x unroll: 4 independent index->feature load chains in flight.
    for (; i + 4 <= cnt; i += 4) {
        int s0 = __ldg(bkt + i + 0);
        int s1 = __ldg(bkt + i + 1);
        int s2 = __ldg(bkt + i + 2);
        int s3 = __ldg(bkt + i + 3);
        float4 v0 = *reinterpret_cast<const float4*>(feat + (long long)s0 * CHANNELS + c4);
        float4 v1 = *reinterpret_cast<const float4*>(feat + (long long)s1 * CHANNELS + c4);
        float4 v2 = *reinterpret_cast<const float4*>(feat + (long long)s2 * CHANNELS + c4);
        float4 v3 = *reinterpret_cast<const float4*>(feat + (long long)s3 * CHANNELS + c4);
        acc = max4(acc, max4(max4(v0, v1), max4(v2, v3)));
    }
    for (; i < cnt; i++) {
        int s = __ldg(bkt + i);
        float4 v = *reinterpret_cast<const float4*>(feat + (long long)s * CHANNELS + c4);
        acc = max4(acc, v);
    }

    // Combine with existing out row (holds -inf, or overflow fallback maxes).
    float4* op = reinterpret_cast<float4*>(out + (long long)p * CHANNELS + c4);
    *op = max4(acc, *op);
}

extern "C" void kernel_launch(void* const* d_in, const int* in_sizes, int n_in,
                              void* d_out, int out_size) {
    const float* feat = (const float*)d_in[0];   // [N_POINTS, 64] f32
    const int* idx = (const int*)d_in[1];        // [N_EDGES, 2] i32
    float* out = (float*)d_out;                  // [N_POINTS, 64] f32

    int n_edges = in_sizes[1] / 2;

    // K1: init out + cursors
    int n4 = out_size / 4;
    int n1 = (n4 > N_POINTS) ? n4 : N_POINTS;
    init_kernel<<<(n1 + 255) / 256, 256>>>((float4*)out, n4);

    // K2: bucket build
    bucket_kernel<<<(n_edges + 255) / 256, 256>>>(idx, feat, out, n_edges);

    // K3: dense per-point max (16 lanes/point)
    long long total = (long long)N_POINTS * 16;
    segmax_kernel<<<(int)((total + 255) / 256), 256>>>(feat, out);
}

// round 4
// speedup vs baseline: 5.7049x; 1.0365x over previous
#include <cuda_runtime.h>
#include <math_constants.h>

#define N_POINTS 50000
#define CHANNELS 64
#define CAP 128           // bucket capacity per point; counts ~Poisson(32), max ~66
#define OVF_CAP (1 << 20) // overflow list capacity (expected usage: 0)

// Static scratch (no allocations allowed).
__device__ int d_cursor[N_POINTS];
__device__ int d_bucket[N_POINTS * CAP];   // 25.6 MB
__device__ int d_ovf_count;
__device__ int d_ovf_list[OVF_CAP];        // edge ids that exceeded CAP

// ---------------------------------------------------------------------------
// K1: zero cursors + overflow counter (out is NOT initialized — K3 writes it
// densely for every point).
// ---------------------------------------------------------------------------
__global__ void init_kernel() {
    int i = blockIdx.x * blockDim.x + threadIdx.x;
    if (i < N_POINTS) d_cursor[i] = 0;
    if (i == 0) d_ovf_count = 0;
}

// Float atomic max via sign-split integer atomics (RED, no return).
// Only used on the (expected-empty) overflow path in K4.
__device__ __forceinline__ void atomicMaxFloat(float* addr, float val) {
    if (val >= 0.0f) {
        atomicMax((int*)addr, __float_as_int(val));
    } else {
        atomicMin((unsigned int*)addr, __float_as_uint(val));
    }
}

// ---------------------------------------------------------------------------
// K2: bucket-build. One thread per TWO edges (int4 index load): claim a slot
// in the destination point's bucket, record the source index. 1.6M atomics.
// Edges whose bucket is full go to the overflow list (processed in K4).
// ---------------------------------------------------------------------------
__device__ __forceinline__ void bucket_one(int e, int o_idx, int i_idx) {
    int pos = atomicAdd(&d_cursor[o_idx], 1);
    if (pos < CAP) {
        d_bucket[o_idx * CAP + pos] = i_idx;
    } else {
        int op = atomicAdd(&d_ovf_count, 1);
        if (op < OVF_CAP) d_ovf_list[op] = e;
    }
}

__global__ void bucket_kernel(const int* __restrict__ idx, int n_edges) {
    int t = blockIdx.x * blockDim.x + threadIdx.x;
    int e0 = t * 2;
    if (e0 >= n_edges) return;

    if (e0 + 1 < n_edges) {
        int4 q = __ldg(reinterpret_cast<const int4*>(idx) + t);
        bucket_one(e0,     q.x, q.y);
        bucket_one(e0 + 1, q.z, q.w);
    } else {
        int2 pr = __ldg(reinterpret_cast<const int2*>(idx) + e0);
        bucket_one(e0, pr.x, pr.y);
    }
}

// ---------------------------------------------------------------------------
// K3: dense segment-max. 16 lanes per point, one float4 (4 channels) per lane.
// Coalesced 256B row gathers from the L2-resident feature table; max entirely
// in registers; WRITE-ONLY store to out (covers every point, incl. empty
// segments -> -inf, so no init pass is needed).
// ---------------------------------------------------------------------------
__device__ __forceinline__ float4 max4(float4 a, float4 b) {
    return make_float4(fmaxf(a.x, b.x), fmaxf(a.y, b.y),
                       fmaxf(a.z, b.z), fmaxf(a.w, b.w));
}

__global__ void segmax_kernel(const float* __restrict__ feat,
                              float* __restrict__ out) {
    int t = blockIdx.x * blockDim.x + threadIdx.x;
    int p = t >> 4;
    if (p >= N_POINTS) return;
    int c4 = (t & 15) << 2;

    int cnt = d_cursor[p];
    if (cnt > CAP) cnt = CAP;
    const int* bkt = d_bucket + p * CAP;

    float4 acc = make_float4(-CUDART_INF_F, -CUDART_INF_F, -CUDART_INF_F, -CUDART_INF_F);

    int i = 0;
    // 4x unroll: 4 independent index->feature load chains in flight per lane.
    for (; i + 4 <= cnt; i += 4) {
        int s0 = __ldg(bkt + i + 0);
        int s1 = __ldg(bkt + i + 1);
        int s2 = __ldg(bkt + i + 2);
        int s3 = __ldg(bkt + i + 3);
        float4 v0 = *reinterpret_cast<const float4*>(feat + (long long)s0 * CHANNELS + c4);
        float4 v1 = *reinterpret_cast<const float4*>(feat + (long long)s1 * CHANNELS + c4);
        float4 v2 = *reinterpret_cast<const float4*>(feat + (long long)s2 * CHANNELS + c4);
        float4 v3 = *reinterpret_cast<const float4*>(feat + (long long)s3 * CHANNELS + c4);
        acc = max4(acc, max4(max4(v0, v1), max4(v2, v3)));
    }
    for (; i < cnt; i++) {
        int s = __ldg(bkt + i);
        float4 v = *reinterpret_cast<const float4*>(feat + (long long)s * CHANNELS + c4);
        acc = max4(acc, v);
    }

    *reinterpret_cast<float4*>(out + (long long)p * CHANNELS + c4) = acc;
}

// ---------------------------------------------------------------------------
// K4: apply overflow edges (expected count 0). Grid-stride over count*16 lane
// tasks; RED atomic-max into the already-written out.
// ---------------------------------------------------------------------------
__global__ void overflow_kernel(const float* __restrict__ feat,
                                const int* __restrict__ idx,
                                float* __restrict__ out) {
    int cnt = d_ovf_count;
    if (cnt > OVF_CAP) cnt = OVF_CAP;
    long long total = (long long)cnt * 16;
    for (long long w = (long long)blockIdx.x * blockDim.x + threadIdx.x;
         w < total; w += (long long)gridDim.x * blockDim.x) {
        int k = (int)(w >> 4);
        int c4 = (int)(w & 15) << 2;
        int e = d_ovf_list[k];
        int2 pr = __ldg(reinterpret_cast<const int2*>(idx) + e);
        float4 v = *reinterpret_cast<const float4*>(feat + (long long)pr.y * CHANNELS + c4);
        float* dst = out + (long long)pr.x * CHANNELS + c4;
        atomicMaxFloat(dst + 0, v.x);
        atomicMaxFloat(dst + 1, v.y);
        atomicMaxFloat(dst + 2, v.z);
        atomicMaxFloat(dst + 3, v.w);
    }
}

extern "C" void kernel_launch(void* const* d_in, const int* in_sizes, int n_in,
                              void* d_out, int out_size) {
    const float* feat = (const float*)d_in[0];   // [N_POINTS, 64] f32
    const int* idx = (const int*)d_in[1];        // [N_EDGES, 2] i32
    float* out = (float*)d_out;                  // [N_POINTS, 64] f32

    int n_edges = in_sizes[1] / 2;

    // K1: zero cursors + overflow counter
    init_kernel<<<(N_POINTS + 255) / 256, 256>>>();

    // K2: bucket build (2 edges / thread)
    int nt2 = (n_edges + 1) / 2;
    bucket_kernel<<<(nt2 + 255) / 256, 256>>>(idx, n_edges);

    // K3: dense per-point max (16 lanes/point), write-only out
    long long total = (long long)N_POINTS * 16;
    segmax_kernel<<<(int)((total + 255) / 256), 256>>>(feat, out);

    // K4: overflow fixup (normally empty)
    overflow_kernel<<<64, 256>>>(feat, idx, out);
}

// round 5
// speedup vs baseline: 5.8829x; 1.0312x over previous
#include <cuda_runtime.h>
#include <math_constants.h>

#define N_POINTS 50000
#define CHANNELS 64
#define CAP 128           // bucket capacity per point; counts ~Poisson(32), max ~66
#define OVF_CAP (1 << 20) // overflow list capacity (expected usage: 0)

// Static scratch (no allocations allowed).
__device__ int d_cursor[N_POINTS];
__device__ int d_bucket[N_POINTS * CAP];   // 25.6 MB, 512B-aligned rows
__device__ int d_ovf_count;
__device__ int d_ovf_list[OVF_CAP];        // edge ids that exceeded CAP

// ---------------------------------------------------------------------------
// K1: zero cursors + overflow counter (out is NOT initialized — K3 writes it
// densely for every point).
// ---------------------------------------------------------------------------
__global__ void init_kernel() {
    int i = blockIdx.x * blockDim.x + threadIdx.x;
    if (i < N_POINTS) d_cursor[i] = 0;
    if (i == 0) d_ovf_count = 0;
}

// ---------------------------------------------------------------------------
// K2: bucket-build. One thread per TWO edges (int4 index load): claim a slot
// in the destination point's bucket, record the source index. 1.6M atomics.
// Edges whose bucket is full go to the overflow list (handled inside K3).
// ---------------------------------------------------------------------------
__device__ __forceinline__ void bucket_one(int e, int o_idx, int i_idx) {
    int pos = atomicAdd(&d_cursor[o_idx], 1);
    if (pos < CAP) {
        d_bucket[o_idx * CAP + pos] = i_idx;
    } else {
        int op = atomicAdd(&d_ovf_count, 1);
        if (op < OVF_CAP) d_ovf_list[op] = e;
    }
}

__global__ void bucket_kernel(const int* __restrict__ idx, int n_edges) {
    int t = blockIdx.x * blockDim.x + threadIdx.x;
    int e0 = t * 2;
    if (e0 >= n_edges) return;

    if (e0 + 1 < n_edges) {
        int4 q = __ldg(reinterpret_cast<const int4*>(idx) + t);
        bucket_one(e0,     q.x, q.y);
        bucket_one(e0 + 1, q.z, q.w);
    } else {
        int2 pr = __ldg(reinterpret_cast<const int2*>(idx) + e0);
        bucket_one(e0, pr.x, pr.y);
    }
}

// ---------------------------------------------------------------------------
// K3: dense segment-max. 16 lanes per point, one float4 (4 channels) per lane.
// Coalesced 256B row gathers from the L2-resident feature table; max entirely
// in registers; write-only store to out (covers every point, incl. empty
// segments -> -inf). Overflow edges (expected: none) are folded in via a
// guarded scan of the overflow list before the store — no separate kernel.
// ---------------------------------------------------------------------------
__device__ __forceinline__ float4 max4(float4 a, float4 b) {
    return make_float4(fmaxf(a.x, b.x), fmaxf(a.y, b.y),
                       fmaxf(a.z, b.z), fmaxf(a.w, b.w));
}

__global__ void segmax_kernel(const float* __restrict__ feat,
                              const int* __restrict__ idx,
                              float* __restrict__ out) {
    int t = blockIdx.x * blockDim.x + threadIdx.x;
    int p = t >> 4;
    if (p >= N_POINTS) return;
    int c4 = (t & 15) << 2;

    int cnt = d_cursor[p];
    if (cnt > CAP) cnt = CAP;
    const int* bkt = d_bucket + p * CAP;   // 512B-aligned

    float4 acc = make_float4(-CUDART_INF_F, -CUDART_INF_F, -CUDART_INF_F, -CUDART_INF_F);

    int i = 0;
    // 4 indices per LDG (int4), 4 independent feature-row chains in flight.
    for (; i + 4 <= cnt; i += 4) {
        int4 s = __ldg(reinterpret_cast<const int4*>(bkt + i));
        float4 v0 = *reinterpret_cast<const float4*>(feat + (long long)s.x * CHANNELS + c4);
        float4 v1 = *reinterpret_cast<const float4*>(feat + (long long)s.y * CHANNELS + c4);
        float4 v2 = *reinterpret_cast<const float4*>(feat + (long long)s.z * CHANNELS + c4);
        float4 v3 = *reinterpret_cast<const float4*>(feat + (long long)s.w * CHANNELS + c4);
        acc = max4(acc, max4(max4(v0, v1), max4(v2, v3)));
    }
    for (; i < cnt; i++) {
        int s = __ldg(bkt + i);
        float4 v = *reinterpret_cast<const float4*>(feat + (long long)s * CHANNELS + c4);
        acc = max4(acc, v);
    }

    // Exactness guard: fold in any overflow edges targeting this point.
    // d_ovf_count is a single L2-hot broadcast load; the branch is ~never taken.
    int ovf = d_ovf_count;
    if (ovf > 0) {
        if (ovf > OVF_CAP) ovf = OVF_CAP;
        for (int j = 0; j < ovf; j++) {
            int e = d_ovf_list[j];
            int2 pr = __ldg(reinterpret_cast<const int2*>(idx) + e);
            if (pr.x == p) {
                float4 v = *reinterpret_cast<const float4*>(feat + (long long)pr.y * CHANNELS + c4);
                acc = max4(acc, v);
            }
        }
    }

    *reinterpret_cast<float4*>(out + (long long)p * CHANNELS + c4) = acc;
}

extern "C" void kernel_launch(void* const* d_in, const int* in_sizes, int n_in,
                              void* d_out, int out_size) {
    const float* feat = (const float*)d_in[0];   // [N_POINTS, 64] f32
    const int* idx = (const int*)d_in[1];        // [N_EDGES, 2] i32
    float* out = (float*)d_out;                  // [N_POINTS, 64] f32

    int n_edges = in_sizes[1] / 2;

    // K1: zero cursors + overflow counter
    init_kernel<<<(N_POINTS + 255) / 256, 256>>>();

    // K2: bucket build (2 edges / thread)
    int nt2 = (n_edges + 1) / 2;
    bucket_kernel<<<(nt2 + 255) / 256, 256>>>(idx, n_edges);

    // K3: dense per-point max (16 lanes/point) + inline overflow fixup
    long long total = (long long)N_POINTS * 16;
    segmax_kernel<<<(int)((total + 255) / 256), 256>>>(feat, idx, out);
}